// round 7
// baseline (speedup 1.0000x reference)
#include <cuda_runtime.h>
#include <cuda_bf16.h>

// TELIF: temporal-encoded LIF spiking neuron scan.
// tx: [T, B, N] f32, TE: [N, T] f32 -> ty: [T, B, N] f32.
//
// R7: float4 — 4 neurons per thread. Six rounds of evidence say the wall is
// the per-warp memory-op count through the LSU/L1tex port (R5: measured
// 1950-cyc chunk period == summed LSU issue cost; DRAM idle 57%), so the
// lever is FEWER, WIDER ops: LDG.128/STG.128 cut ops-per-byte 2x vs the
// float2 R3 kernel (the only variant that improved the scan). Everything
// else identical to R3. Single launch; 512 blocks of 32.

#define T_STEPS 512
#define B_DIM   64
#define N_DIM   1024
#define BN      (B_DIM * N_DIM)

#define REST      0.0f
#define DECAY     0.2f
#define THRESHOLD 0.3f
#define BETA      0.02f

#define UNROLL 8

__device__ float g_te_t[T_STEPS * N_DIM];  // TE transposed to [T][N]

// ---------------------------------------------------------------------------
// Transpose TE [N, T] -> g_te_t [T, N]. 32x32 tiles, padded smem.
// ---------------------------------------------------------------------------
__global__ void telif_transpose_te(const float* __restrict__ TE) {
    __shared__ float tile[32][33];
    int n0 = blockIdx.x * 32;
    int t0 = blockIdx.y * 32;
    int lx = threadIdx.x;
    int ly = threadIdx.y;

#pragma unroll
    for (int i = 0; i < 32; i += 8)
        tile[ly + i][lx] = TE[(size_t)(n0 + ly + i) * T_STEPS + (t0 + lx)];
    __syncthreads();
#pragma unroll
    for (int i = 0; i < 32; i += 8)
        g_te_t[(size_t)(t0 + ly + i) * N_DIM + (n0 + lx)] = tile[lx][ly + i];
}

// ---------------------------------------------------------------------------
// Main scan. One thread per 4 adjacent (b, n) lanes; float4 everywhere.
// 16384 threads, 512 blocks of 32.
// ---------------------------------------------------------------------------
__global__ void __launch_bounds__(32)
telif_scan(const float4* __restrict__ tx4, float4* __restrict__ out4) {
    const int gid = blockIdx.x * 32 + threadIdx.x;      // quad index
    const int n4  = gid & (N_DIM / 4 - 1);              // quad index within N

    const float4* txp = tx4 + gid;
    float4*       op  = out4 + gid;
    const float4* tep = reinterpret_cast<const float4*>(g_te_t) + n4;

    float4 v  = make_float4(REST, REST, REST, REST);
    float4 y  = make_float4(0.0f, 0.0f, 0.0f, 0.0f);
    float4 th = make_float4(THRESHOLD, THRESHOLD, THRESHOLD, THRESHOLD);

#pragma unroll 1
    for (int t0 = 0; t0 < T_STEPS; t0 += UNROLL) {
        float4 xs[UNROLL], te[UNROLL];
        // Front-batched: 16 outstanding LDG.128 per thread (8 KB/warp).
#pragma unroll
        for (int u = 0; u < UNROLL; u++) {
            xs[u] = txp[(size_t)(t0 + u) * (BN / 4)];
            te[u] = tep[(size_t)(t0 + u) * (N_DIM / 4)];
        }
        // Four independent chains -> ILP 4 on the serial recurrence path.
#pragma unroll
        for (int u = 0; u < UNROLL; u++) {
            th.x = th.x + v.x * te[u].x - (th.x - THRESHOLD) * BETA;
            th.y = th.y + v.y * te[u].y - (th.y - THRESHOLD) * BETA;
            th.z = th.z + v.z * te[u].z - (th.z - THRESHOLD) * BETA;
            th.w = th.w + v.w * te[u].w - (th.w - THRESHOLD) * BETA;

            v.x = v.x * DECAY * (1.0f - y.x) + xs[u].x;
            v.y = v.y * DECAY * (1.0f - y.y) + xs[u].y;
            v.z = v.z * DECAY * (1.0f - y.z) + xs[u].z;
            v.w = v.w * DECAY * (1.0f - y.w) + xs[u].w;

            y.x = (v.x > th.x) ? 1.0f : 0.0f;
            y.y = (v.y > th.y) ? 1.0f : 0.0f;
            y.z = (v.z > th.z) ? 1.0f : 0.0f;
            y.w = (v.w > th.w) ? 1.0f : 0.0f;

            op[(size_t)(t0 + u) * (BN / 4)] = y;   // STG.128
        }
    }
}

// ---------------------------------------------------------------------------
// Launch
// ---------------------------------------------------------------------------
extern "C" void kernel_launch(void* const* d_in, const int* in_sizes, int n_in,
                              void* d_out, int out_size) {
    const float* tx = (const float*)d_in[0];   // [T, B, N]
    const float* TE = (const float*)d_in[1];   // [N, T]
    float* out = (float*)d_out;                // [T, B, N]

    (void)in_sizes; (void)n_in; (void)out_size;

    dim3 tb(32, 8);
    dim3 tg(N_DIM / 32, T_STEPS / 32);
    telif_transpose_te<<<tg, tb>>>(TE);

    telif_scan<<<(BN / 4) / 32, 32>>>(
        reinterpret_cast<const float4*>(tx),
        reinterpret_cast<float4*>(out));
}

// round 8
// speedup vs baseline: 1.9329x; 1.9329x over previous
#include <cuda_runtime.h>
#include <cuda_bf16.h>
#include <cstdint>

// TELIF: temporal-encoded LIF spiking neuron scan.
// tx: [T, B, N] f32, TE: [N, T] f32 -> ty: [T, B, N] f32.
//
// R8: warp-specialized producer/consumer. 2048 compute lanes cap occupancy at
// 13.8 warps/SM; every same-warp prefetch scheme (reg batch, cp.async) kept
// in-flight bytes ~1 chunk/warp because the issuing warp also computes.
// Fix: per 32 neurons, a producer warp (pure cp.async.cg pump into a 6-stage
// mbarrier ring, lag-4 commit-group arrival) + a consumer warp (LDS -> LIF
// chain -> STG). 27.7 warps/SM; producers hold ~165 KB/SM in flight.

#define T_STEPS 512
#define B_DIM   64
#define N_DIM   1024
#define BN      (B_DIM * N_DIM)

#define REST      0.0f
#define DECAY     0.2f
#define THRESHOLD 0.3f
#define BETA      0.02f

#define CHUNK    8                    // time steps per stage
#define NCHUNK   (T_STEPS / CHUNK)    // 64
#define STAGES   6
#define LAG      4                    // commit-group completion lag
#define PAIRS    2                    // warp pairs per block
#define BLKT     (PAIRS * 64)         // 128 threads: warps 0,1 prod; 2,3 cons

__device__ float g_te_t[T_STEPS * N_DIM];   // TE transposed to [T][N]

// ---------------------------------------------------------------------------
// Transpose TE [N, T] -> g_te_t [T, N].
// ---------------------------------------------------------------------------
__global__ void telif_transpose_te(const float* __restrict__ TE) {
    __shared__ float tile[32][33];
    int n0 = blockIdx.x * 32;
    int t0 = blockIdx.y * 32;
    int lx = threadIdx.x;
    int ly = threadIdx.y;

#pragma unroll
    for (int i = 0; i < 32; i += 8)
        tile[ly + i][lx] = TE[(size_t)(n0 + ly + i) * T_STEPS + (t0 + lx)];
    __syncthreads();
#pragma unroll
    for (int i = 0; i < 32; i += 8)
        g_te_t[(size_t)(t0 + ly + i) * N_DIM + (n0 + lx)] = tile[lx][ly + i];
}

// ---------------------------------------------------------------------------
// PTX helpers
// ---------------------------------------------------------------------------
__device__ __forceinline__ uint32_t smem_u32(const void* p) {
    return (uint32_t)__cvta_generic_to_shared(p);
}
__device__ __forceinline__ void cp_async16(uint32_t saddr, const void* gptr) {
    asm volatile("cp.async.cg.shared.global [%0], [%1], 16;\n"
                 :: "r"(saddr), "l"(gptr));
}
__device__ __forceinline__ void cp_commit() {
    asm volatile("cp.async.commit_group;\n");
}
__device__ __forceinline__ void cp_wait_lag() {
    asm volatile("cp.async.wait_group 4;\n" ::: "memory");
}
__device__ __forceinline__ void cp_wait_all() {
    asm volatile("cp.async.wait_group 0;\n" ::: "memory");
}
__device__ __forceinline__ void mbar_init(uint32_t a, uint32_t cnt) {
    asm volatile("mbarrier.init.shared.b64 [%0], %1;\n" :: "r"(a), "r"(cnt) : "memory");
}
__device__ __forceinline__ void mbar_arrive(uint32_t a) {
    asm volatile("mbarrier.arrive.release.cta.shared::cta.b64 _, [%0];\n"
                 :: "r"(a) : "memory");
}
__device__ __forceinline__ void mbar_wait(uint32_t a, uint32_t phase) {
    uint32_t done;
    asm volatile(
        "{\n\t.reg .pred p;\n\t"
        "mbarrier.try_wait.parity.acquire.cta.shared::cta.b64 p, [%1], %2;\n\t"
        "selp.b32 %0, 1, 0, p;\n\t}"
        : "=r"(done) : "r"(a), "r"(phase) : "memory");
    if (!done) {
        asm volatile(
            "{\n\t.reg .pred P1;\n\t"
            "WL_%=:\n\t"
            "mbarrier.try_wait.parity.acquire.cta.shared::cta.b64 P1, [%0], %1;\n\t"
            "@P1 bra.uni WD_%=;\n\t"
            "bra.uni WL_%=;\n\t"
            "WD_%=:\n\t}"
            :: "r"(a), "r"(phase) : "memory");
    }
}

// ---------------------------------------------------------------------------
// Main scan: producer/consumer warp pairs over 32 neurons each.
// smem stage layout: [pair][stage][arr(tx=0,te=1)][step][lane]
// ---------------------------------------------------------------------------
__global__ void __launch_bounds__(BLKT)
telif_scan(const float* __restrict__ tx, float* __restrict__ out) {
    __shared__ __align__(16) float stg[PAIRS][STAGES][2][CHUNK][32];
    __shared__ __align__(8)  uint64_t mb_full[PAIRS][STAGES];
    __shared__ __align__(8)  uint64_t mb_empty[PAIRS][STAGES];

    const int tid  = threadIdx.x;
    const int wid  = tid >> 5;
    const int lane = tid & 31;
    const bool producer = (wid < PAIRS);
    const int p = producer ? wid : (wid - PAIRS);

    const int blockbase = blockIdx.x * (PAIRS * 32);
    const int pairbase  = blockbase + p * 32;

    if (tid == 0) {
#pragma unroll
        for (int q = 0; q < PAIRS; q++)
#pragma unroll
            for (int s = 0; s < STAGES; s++) {
                mbar_init(smem_u32(&mb_full[q][s]), 32);
                mbar_init(smem_u32(&mb_empty[q][s]), 32);
            }
    }
    __syncthreads();

    if (producer) {
        // ------------------ producer warp: pure memory pump ------------------
        const float* txb = tx + pairbase;
        const float* teb = g_te_t + (pairbase & (N_DIM - 1));

        // cp.async split: k = lane + 32j -> step st = k>>3, 16B seg = k&7.
        const int k0  = lane;
        const int k1  = lane + 32;
        const int st0 = k0 >> 3, sg0 = (k0 & 7) * 4;   // seg offset in floats
        const int st1 = k1 >> 3, sg1 = (k1 & 7) * 4;

        int es = 0, eph = 1;     // empty-wait cursor (Pipeline convention)
        int as = 0;              // full-arrive cursor (lags by LAG)

#pragma unroll 1
        for (int c = 0; c < NCHUNK; c++) {
            mbar_wait(smem_u32(&mb_empty[p][es]), eph);

            const float* ctx = txb + (size_t)(c * CHUNK) * BN;
            const float* cte = teb + (size_t)(c * CHUNK) * N_DIM;
            cp_async16(smem_u32(&stg[p][es][0][st0][sg0]), ctx + (size_t)st0 * BN + sg0);
            cp_async16(smem_u32(&stg[p][es][1][st0][sg0]), cte + (size_t)st0 * N_DIM + sg0);
            cp_async16(smem_u32(&stg[p][es][0][st1][sg1]), ctx + (size_t)st1 * BN + sg1);
            cp_async16(smem_u32(&stg[p][es][1][st1][sg1]), cte + (size_t)st1 * N_DIM + sg1);
            cp_commit();

            if (c >= LAG) {
                cp_wait_lag();                       // group c-LAG complete
                mbar_arrive(smem_u32(&mb_full[p][as]));
                if (++as == STAGES) as = 0;
            }
            if (++es == STAGES) { es = 0; eph ^= 1; }
        }
        // Tail: flush last LAG chunks.
        cp_wait_all();
#pragma unroll
        for (int r = 0; r < LAG; r++) {
            mbar_arrive(smem_u32(&mb_full[p][as]));
            if (++as == STAGES) as = 0;
        }
    } else {
        // ------------------ consumer warp: LDS -> LIF -> STG -----------------
        const int idx = pairbase + lane;
        float* op = out + idx;

        float v  = REST;
        float y  = 0.0f;
        float th = THRESHOLD;

        int fs = 0, fph = 0;     // full-wait cursor

#pragma unroll 1
        for (int c = 0; c < NCHUNK; c++) {
            mbar_wait(smem_u32(&mb_full[p][fs]), fph);

            float xr[CHUNK], tr[CHUNK];
#pragma unroll
            for (int s = 0; s < CHUNK; s++) {
                xr[s] = stg[p][fs][0][s][lane];
                tr[s] = stg[p][fs][1][s][lane];
            }

#pragma unroll
            for (int s = 0; s < CHUNK; s++) {
                th = th + v * tr[s] - (th - THRESHOLD) * BETA;
                v  = v * DECAY * (1.0f - y) + xr[s];
                y  = (v > th) ? 1.0f : 0.0f;
                op[(size_t)(c * CHUNK + s) * BN] = y;
            }

            mbar_arrive(smem_u32(&mb_empty[p][fs]));
            if (++fs == STAGES) { fs = 0; fph ^= 1; }
        }
    }
}

// ---------------------------------------------------------------------------
// Launch
// ---------------------------------------------------------------------------
extern "C" void kernel_launch(void* const* d_in, const int* in_sizes, int n_in,
                              void* d_out, int out_size) {
    const float* tx = (const float*)d_in[0];   // [T, B, N]
    const float* TE = (const float*)d_in[1];   // [N, T]
    float* out = (float*)d_out;                // [T, B, N]

    (void)in_sizes; (void)n_in; (void)out_size;

    dim3 tb(32, 8);
    dim3 tg(N_DIM / 32, T_STEPS / 32);
    telif_transpose_te<<<tg, tb>>>(TE);

    telif_scan<<<BN / (PAIRS * 32), BLKT>>>(tx, out);
}